// round 8
// baseline (speedup 1.0000x reference)
#include <cuda_runtime.h>
#include <math.h>
#include <stdint.h>

// Problem constants
constexpr int kT = 4096;
constexpr int kC = 2048;
constexpr int kH = 16;
constexpr int kD = 128;
constexpr float kScale = 0.08838834764831845f;

// Scratch (device globals — no cudaMalloc allowed)
__device__ float g_q[kT * kC];
__device__ float g_k[kT * kC];
__device__ float g_v[kT * kC];
__device__ float g_ctx[kT * kC];
__device__ float g_xr[kT * kC];          // tf32-rounded x
__device__ float g_wr[4 * kC * kC];      // tf32-rounded wq,wk,wv,wo

// ---------------------------------------------------------------------------
__device__ __forceinline__ uint32_t smem_u32(const void* p) {
    uint32_t a;
    asm("{ .reg .u64 t; cvta.to.shared.u64 t, %1; cvt.u32.u64 %0, t; }"
        : "=r"(a) : "l"(p));
    return a;
}

__device__ __forceinline__ void cp_async16(uint32_t saddr, const void* gaddr) {
    asm volatile("cp.async.cg.shared.global [%0], [%1], 16;"
                 :: "r"(saddr), "l"(gaddr));
}
#define CP_COMMIT() asm volatile("cp.async.commit_group;" ::: "memory")

__device__ __forceinline__ float round_tf32(float x) {
    uint32_t u;
    asm("cvt.rna.tf32.f32 %0, %1;" : "=r"(u) : "f"(x));
    return __uint_as_float(u);
}

// mma.sync m16n8k8 tf32: D(16x8 f32) += A(16x8) * B(8x8)
__device__ __forceinline__ void mma_tf32(float* d, const uint32_t* a,
                                         const uint32_t* b) {
    asm volatile(
        "mma.sync.aligned.m16n8k8.row.col.f32.tf32.tf32.f32 "
        "{%0,%1,%2,%3}, {%4,%5,%6,%7}, {%8,%9}, {%0,%1,%2,%3};"
        : "+f"(d[0]), "+f"(d[1]), "+f"(d[2]), "+f"(d[3])
        : "r"(a[0]), "r"(a[1]), "r"(a[2]), "r"(a[3]), "r"(b[0]), "r"(b[1]));
}

// ---------------------------------------------------------------------------
// Fused elementwise tf32 rounding: y=0 -> x, y in 1..4 -> weights.
// ---------------------------------------------------------------------------
__global__ void round_all(const float* __restrict__ x,
                          const float* __restrict__ wq,
                          const float* __restrict__ wk,
                          const float* __restrict__ wv,
                          const float* __restrict__ wo,
                          float* __restrict__ xr, float* __restrict__ wr) {
    const int y = blockIdx.y;
    const float* src;
    float* dst;
    int n4;
    const int CC = kC * kC;
    if (y == 0) { src = x;  dst = xr;           n4 = kT * kC / 4; }
    else if (y == 1) { src = wq; dst = wr;          n4 = CC / 4; }
    else if (y == 2) { src = wk; dst = wr + CC;     n4 = CC / 4; }
    else if (y == 3) { src = wv; dst = wr + 2 * CC; n4 = CC / 4; }
    else             { src = wo; dst = wr + 3 * CC; n4 = CC / 4; }
    int i = blockIdx.x * blockDim.x + threadIdx.x;
    if (i < n4) {
        float4 v = ((const float4*)src)[i];
        v.x = round_tf32(v.x); v.y = round_tf32(v.y);
        v.z = round_tf32(v.z); v.w = round_tf32(v.w);
        ((float4*)dst)[i] = v;
    }
}

// ---------------------------------------------------------------------------
// TF32 tensor-core GEMM: C[m,n] = sum_k A[m,k] * B[n,k]
// CTA tile 128x128x32, 3-stage cp.async pipeline, XOR-swizzled smem.
// blockIdx.z selects among up to 3 (B, C) pairs. roundMask bit z: round output.
// ---------------------------------------------------------------------------
constexpr int GLD = 32;
constexpr int GSTAGE_FLOATS = 2 * 128 * GLD;
constexpr int GEMM_SMEM_BYTES = 3 * GSTAGE_FLOATS * 4;  // 98304

__device__ __forceinline__ int swoff(int r, int c) {
    return r * GLD + ((((c >> 2) ^ (r & 7)) << 2) | (c & 3));
}

__global__ __launch_bounds__(256, 2) void gemm_tc3(
    const float* __restrict__ A,
    const float* __restrict__ B0, const float* __restrict__ B1,
    const float* __restrict__ B2,
    float* __restrict__ C0, float* __restrict__ C1, float* __restrict__ C2,
    int M, int N, int K, unsigned roundMask) {
    const float* B = (blockIdx.z == 0) ? B0 : (blockIdx.z == 1) ? B1 : B2;
    float* C = (blockIdx.z == 0) ? C0 : (blockIdx.z == 1) ? C1 : C2;
    const bool doRound = (roundMask >> blockIdx.z) & 1u;

    extern __shared__ float smf[];
    const uint32_t sb = smem_u32(smf);
    const int tid = threadIdx.x;
    const int lane = tid & 31;
    const int wid = tid >> 5;
    const int warp_m = wid & 3;
    const int warp_n = wid >> 2;
    const int bm = blockIdx.y * 128;
    const int bn = blockIdx.x * 128;

    const int lrow = tid >> 3;
    const int cc8 = tid & 7;

    float d[2][8][4];
#pragma unroll
    for (int mi = 0; mi < 2; mi++)
#pragma unroll
        for (int ni = 0; ni < 8; ni++)
#pragma unroll
            for (int j = 0; j < 4; j++) d[mi][ni][j] = 0.0f;

    const int nStages = K / 32;

    auto prefetch = [&](int s) {
        const int buf = s % 3;
        const uint32_t ab = sb + buf * GSTAGE_FLOATS * 4;
        const uint32_t bb = ab + 128 * GLD * 4;
        const int k0 = s * 32;
#pragma unroll
        for (int j = 0; j < 4; j++) {
            const int row = lrow + j * 32;
            const int scc = cc8 ^ (row & 7);
            const uint32_t soff = (uint32_t)(row * GLD + scc * 4) * 4;
            cp_async16(ab + soff, &A[(size_t)(bm + row) * K + k0 + cc8 * 4]);
            cp_async16(bb + soff, &B[(size_t)(bn + row) * K + k0 + cc8 * 4]);
        }
        CP_COMMIT();
    };

    prefetch(0);
    prefetch(1);

    const int fr = lane >> 2;
    const int fc = lane & 3;

    for (int s = 0; s < nStages; s++) {
        if (s < nStages - 1) {
            asm volatile("cp.async.wait_group 1;" ::: "memory");
        } else {
            asm volatile("cp.async.wait_group 0;" ::: "memory");
        }
        __syncthreads();
        if (s + 2 < nStages) prefetch(s + 2);

        const int buf = s % 3;
        const uint32_t* As = (const uint32_t*)(smf + buf * GSTAGE_FLOATS);
        const uint32_t* Bs = As + 128 * GLD;

#pragma unroll
        for (int kk = 0; kk < 4; kk++) {
            const int c0 = kk * 8 + fc;
            uint32_t a[2][4];
#pragma unroll
            for (int mi = 0; mi < 2; mi++) {
                const int r0 = warp_m * 32 + mi * 16 + fr;
                a[mi][0] = As[swoff(r0, c0)];
                a[mi][1] = As[swoff(r0 + 8, c0)];
                a[mi][2] = As[swoff(r0, c0 + 4)];
                a[mi][3] = As[swoff(r0 + 8, c0 + 4)];
            }
            uint32_t b[8][2];
#pragma unroll
            for (int ni = 0; ni < 8; ni++) {
                const int n0 = warp_n * 64 + ni * 8 + fr;
                b[ni][0] = Bs[swoff(n0, c0)];
                b[ni][1] = Bs[swoff(n0, c0 + 4)];
            }
#pragma unroll
            for (int mi = 0; mi < 2; mi++)
#pragma unroll
                for (int ni = 0; ni < 8; ni++)
                    mma_tf32(d[mi][ni], a[mi], b[ni]);
        }
    }

#pragma unroll
    for (int mi = 0; mi < 2; mi++) {
        const int row = bm + warp_m * 32 + mi * 16 + fr;
#pragma unroll
        for (int ni = 0; ni < 8; ni++) {
            const int col = bn + warp_n * 64 + ni * 8 + fc * 2;
            float2 v0 = make_float2(d[mi][ni][0], d[mi][ni][1]);
            float2 v1 = make_float2(d[mi][ni][2], d[mi][ni][3]);
            if (doRound) {
                v0.x = round_tf32(v0.x); v0.y = round_tf32(v0.y);
                v1.x = round_tf32(v1.x); v1.y = round_tf32(v1.y);
            }
            *(float2*)&C[(size_t)row * N + col] = v0;
            *(float2*)&C[(size_t)(row + 8) * N + col] = v1;
        }
    }
}

// ---------------------------------------------------------------------------
// RoPE in-place on Q and K laid out [T, H*D].
// Q: rotated, scaled by kScale, tf32-rounded. K: rotated, tf32-rounded.
// ---------------------------------------------------------------------------
__global__ void rope_kernel(float* __restrict__ Q, float* __restrict__ K) {
    const int t = blockIdx.x;
    const float ft = (float)t;
    for (int p = threadIdx.x; p < kH * 64; p += blockDim.x) {
        const int h = p >> 6;
        const int i = p & 63;
        const float inv = __expf(-(float)i * 0.14391157f);
        float s, c;
        sincosf(ft * inv, &s, &c);
        const size_t base = (size_t)t * kC + h * kD;
        {
            float x1 = Q[base + i], x2 = Q[base + 64 + i];
            Q[base + i]      = round_tf32((x1 * c - x2 * s) * kScale);
            Q[base + 64 + i] = round_tf32((x2 * c + x1 * s) * kScale);
        }
        {
            float x1 = K[base + i], x2 = K[base + 64 + i];
            K[base + i]      = round_tf32(x1 * c - x2 * s);
            K[base + 64 + i] = round_tf32(x2 * c + x1 * s);
        }
    }
}

// ---------------------------------------------------------------------------
// Tensor-core block-sparse flash attention. One CTA per (q-PAIR, head):
// 128 q rows, 512 threads / 16 warps (4 per SMSP for latency hiding).
// QK warp tile 16x32 (grid 8x2 over 128x64); PV warp tile 16x64 (8x2 over
// 128x128). Software-pipelined cp.async K/V; heavy CTAs first.
// ---------------------------------------------------------------------------
constexpr int AQLD = 132;   // Q [128][132], K [64][132]
constexpr int AVLD = 136;   // V [64][136]
constexpr int APLD = 68;    // S/P [128][68]
constexpr int ATTN_SMEM_FLOATS =
    128 * AQLD + 64 * AQLD + 64 * AVLD + 128 * APLD + 128;
constexpr int ATTN_SMEM_BYTES = ATTN_SMEM_FLOATS * 4;   // 171,520 B

__global__ __launch_bounds__(512, 1) void attn_tc2(const float* __restrict__ Q,
                                                   const float* __restrict__ K,
                                                   const float* __restrict__ V,
                                                   float* __restrict__ Ctx) {
    extern __shared__ float sm[];
    float* Qs = sm;                         // [128][132]
    float* Ks = Qs + 128 * AQLD;            // [64][132]
    float* Vs = Ks + 64 * AQLD;             // [64][136]
    float* Ps = Vs + 64 * AVLD;             // [128][68]
    float* Cr = Ps + 128 * APLD;            // [128]

    const uint32_t sb = smem_u32(sm);
    const uint32_t QsA = sb;
    const uint32_t KsA = sb + 128 * AQLD * 4;
    const uint32_t VsA = KsA + 64 * AQLD * 4;

    const int qp = (gridDim.x - 1) - blockIdx.x;   // heavy-first
    const int h = blockIdx.y;
    const int q0 = 2 * qp;
    const int q1 = q0 + 1;
    const int tid = threadIdx.x;
    const int lane = tid & 31;
    const int wid = tid >> 5;              // 0..15
    const int wm = wid & 7;                // rows wm*16..+15
    const int wn = wid >> 3;               // QK cols wn*32 ; PV dims wn*64
    const int fr = lane >> 2;
    const int fc = lane & 3;
    const int srow = tid >> 2;             // softmax row 0..127
    const int squar = tid & 3;             // softmax col quarter (16 cols)

    auto is_allowed = [&](int t) {
        const bool glob = (t < 2) || ((t & 3) == 0);
        const bool a0 = (t <= q0) && (((q0 - t) <= 16) || glob);
        const bool a1 = ((q1 - t) <= 16) || glob;
        return a0 || a1;
    };

    auto issueK = [&](int t) {
#pragma unroll
        for (int j = 0; j < 4; j++) {
            const int idx = tid * 4 + j * 2048;
            const int rr = idx >> 7;
            const int dd = idx & 127;
            cp_async16(KsA + (uint32_t)(rr * AQLD + dd) * 4,
                       &K[(size_t)(t * 64 + rr) * kC + h * kD + dd]);
        }
        CP_COMMIT();
    };
    auto issueV = [&](int t) {
#pragma unroll
        for (int j = 0; j < 4; j++) {
            const int idx = tid * 4 + j * 2048;
            const int rr = idx >> 7;
            const int dd = idx & 127;
            cp_async16(VsA + (uint32_t)(rr * AVLD + dd) * 4,
                       &V[(size_t)(t * 64 + rr) * kC + h * kD + dd]);
        }
        CP_COMMIT();
    };

    // Q tile (group 0), then K0 (group 1), V0 (group 2)
#pragma unroll
    for (int j = 0; j < 8; j++) {
        const int idx = tid * 4 + j * 2048;
        const int rr = idx >> 7;
        const int dd = idx & 127;
        cp_async16(QsA + (uint32_t)(rr * AQLD + dd) * 4,
                   &Q[(size_t)(qp * 128 + rr) * kC + h * kD + dd]);
    }
    CP_COMMIT();
    int kb = 0;
    issueK(kb);
    issueV(kb);

    float m = -INFINITY, l = 0.0f;
    float o[8][4];
#pragma unroll
    for (int ni = 0; ni < 8; ni++)
#pragma unroll
        for (int j = 0; j < 4; j++) o[ni][j] = 0.0f;

    const uint32_t* Qsu = (const uint32_t*)Qs;
    const uint32_t* Ksu = (const uint32_t*)Ks;
    const uint32_t* Vsu = (const uint32_t*)Vs;
    const uint32_t* Psu = (const uint32_t*)Ps;

    while (true) {
        int kbn = kb;
        for (int t = kb + 1; t <= q1; t++) {
            if (is_allowed(t)) { kbn = t; break; }
        }
        const bool glob = (kb < 2) || ((kb & 3) == 0);
        const bool allowed0 = (kb <= q0) && (((q0 - kb) <= 16) || glob);
        const bool allowed1 = ((q1 - kb) <= 16) || glob;

        // wait for K(kb) (Q on first iter too); V(kb) may still be in flight
        asm volatile("cp.async.wait_group 1;" ::: "memory");
        __syncthreads();

        // ---- S = Q @ K^T (128x64) : warp tile 16x32 ----
        float s[4][4];
#pragma unroll
        for (int ni = 0; ni < 4; ni++)
#pragma unroll
            for (int j = 0; j < 4; j++) s[ni][j] = 0.0f;

#pragma unroll
        for (int kk = 0; kk < 16; kk++) {
            const int c0 = kk * 8 + fc;
            const int r0 = wm * 16 + fr;
            uint32_t a[4];
            a[0] = Qsu[r0 * AQLD + c0];
            a[1] = Qsu[(r0 + 8) * AQLD + c0];
            a[2] = Qsu[r0 * AQLD + c0 + 4];
            a[3] = Qsu[(r0 + 8) * AQLD + c0 + 4];
#pragma unroll
            for (int ni = 0; ni < 4; ni++) {
                const int n0 = wn * 32 + ni * 8 + fr;
                uint32_t b[2];
                b[0] = Ksu[n0 * AQLD + c0];
                b[1] = Ksu[n0 * AQLD + c0 + 4];
                mma_tf32(s[ni], a, b);
            }
        }

        // Store S fragments
        {
            const int r = wm * 16 + fr;
#pragma unroll
            for (int ni = 0; ni < 4; ni++) {
                const int c = wn * 32 + ni * 8 + fc * 2;
                *(float2*)&Ps[r * APLD + c] = make_float2(s[ni][0], s[ni][1]);
                *(float2*)&Ps[(r + 8) * APLD + c] = make_float2(s[ni][2], s[ni][3]);
            }
        }
        __syncthreads();   // all QK reads of Ks done; S visible

        // prefetch next K (overlaps softmax+PV)
        issueK(kbn);

        // ---- scalar online softmax (row srow, cols squar*16..+15) ----
        {
            const bool rowAllowed = (srow < 64) ? allowed0 : allowed1;
            float* prow = &Ps[srow * APLD + squar * 16];
            if (rowAllowed) {
                float4 sv[4];
#pragma unroll
                for (int j = 0; j < 4; j++) sv[j] = *(const float4*)&prow[j * 4];
                float lm = -INFINITY;
#pragma unroll
                for (int j = 0; j < 4; j++)
                    lm = fmaxf(lm, fmaxf(fmaxf(sv[j].x, sv[j].y), fmaxf(sv[j].z, sv[j].w)));
                lm = fmaxf(lm, __shfl_xor_sync(0xFFFFFFFFu, lm, 1));
                lm = fmaxf(lm, __shfl_xor_sync(0xFFFFFFFFu, lm, 2));
                const float mnew = fmaxf(m, lm);
                const float corr = __expf(m - mnew);
                float rs = 0.0f;
#pragma unroll
                for (int j = 0; j < 4; j++) {
                    sv[j].x = round_tf32(__expf(sv[j].x - mnew));
                    sv[j].y = round_tf32(__expf(sv[j].y - mnew));
                    sv[j].z = round_tf32(__expf(sv[j].z - mnew));
                    sv[j].w = round_tf32(__expf(sv[j].w - mnew));
                    rs += (sv[j].x + sv[j].y) + (sv[j].z + sv[j].w);
                    *(float4*)&prow[j * 4] = sv[j];
                }
                rs += __shfl_xor_sync(0xFFFFFFFFu, rs, 1);
                rs += __shfl_xor_sync(0xFFFFFFFFu, rs, 2);
                l = l * corr + rs;
                m = mnew;
                if (squar == 0) Cr[srow] = corr;
            } else {
                const float4 z = make_float4(0.f, 0.f, 0.f, 0.f);
#pragma unroll
                for (int j = 0; j < 4; j++) *(float4*)&prow[j * 4] = z;
                if (squar == 0) Cr[srow] = 1.0f;
            }
        }

        // wait for V(kb) (K(kbn) stays in flight), then publish P/Cr/V
        asm volatile("cp.async.wait_group 1;" ::: "memory");
        __syncthreads();

        // ---- O = O*corr + P @ V (128x128) : warp tile 16x64 ----
        {
            const float c0r = Cr[wm * 16 + fr];
            const float c1r = Cr[wm * 16 + 8 + fr];
#pragma unroll
            for (int ni = 0; ni < 8; ni++) {
                o[ni][0] *= c0r; o[ni][1] *= c0r;
                o[ni][2] *= c1r; o[ni][3] *= c1r;
            }
        }
#pragma unroll
        for (int kk = 0; kk < 8; kk++) {
            const int c0 = kk * 8 + fc;
            const int r0 = wm * 16 + fr;
            uint32_t a[4];
            a[0] = Psu[r0 * APLD + c0];
            a[1] = Psu[(r0 + 8) * APLD + c0];
            a[2] = Psu[r0 * APLD + c0 + 4];
            a[3] = Psu[(r0 + 8) * APLD + c0 + 4];
#pragma unroll
            for (int ni = 0; ni < 8; ni++) {
                const int n0 = wn * 64 + ni * 8 + fr;
                uint32_t b[2];
                b[0] = Vsu[c0 * AVLD + n0];
                b[1] = Vsu[(c0 + 4) * AVLD + n0];
                mma_tf32(o[ni], a, b);
            }
        }
        __syncthreads();   // PV reads of Vs/Ps done

        // prefetch next V (overlaps next tile's QK+softmax)
        issueV(kbn);

        if (kbn == kb) break;
        kb = kbn;
    }

    // Drain, publish 1/l, store
    asm volatile("cp.async.wait_group 0;" ::: "memory");
    __syncthreads();
    if (squar == 0) Cr[srow] = 1.0f / l;
    __syncthreads();
    {
        const float inv0 = Cr[wm * 16 + fr];
        const float inv1 = Cr[wm * 16 + 8 + fr];
        const int row0 = qp * 128 + wm * 16 + fr;
#pragma unroll
        for (int ni = 0; ni < 8; ni++) {
            const int col = h * kD + wn * 64 + ni * 8 + fc * 2;
            *(float2*)&Ctx[(size_t)row0 * kC + col] =
                make_float2(round_tf32(o[ni][0] * inv0),
                            round_tf32(o[ni][1] * inv0));
            *(float2*)&Ctx[(size_t)(row0 + 8) * kC + col] =
                make_float2(round_tf32(o[ni][2] * inv1),
                            round_tf32(o[ni][3] * inv1));
        }
    }
}

// ---------------------------------------------------------------------------
extern "C" void kernel_launch(void* const* d_in, const int* in_sizes, int n_in,
                              void* d_out, int out_size) {
    const float* x  = (const float*)d_in[0];
    const float* wq = (const float*)d_in[1];
    const float* wk = (const float*)d_in[2];
    const float* wv = (const float*)d_in[3];
    const float* wo = (const float*)d_in[4];
    float* out = (float*)d_out;

    float *qp, *kp, *vp, *cp, *xr, *wr;
    cudaGetSymbolAddress((void**)&qp, g_q);
    cudaGetSymbolAddress((void**)&kp, g_k);
    cudaGetSymbolAddress((void**)&vp, g_v);
    cudaGetSymbolAddress((void**)&cp, g_ctx);
    cudaGetSymbolAddress((void**)&xr, g_xr);
    cudaGetSymbolAddress((void**)&wr, g_wr);

    cudaFuncSetAttribute(gemm_tc3, cudaFuncAttributeMaxDynamicSharedMemorySize,
                         GEMM_SMEM_BYTES);
    cudaFuncSetAttribute(attn_tc2, cudaFuncAttributeMaxDynamicSharedMemorySize,
                         ATTN_SMEM_BYTES);

    const int CC = kC * kC;

    round_all<<<dim3(kT * kC / 4 / 256, 5), 256>>>(x, wq, wk, wv, wo, xr, wr);

    // Fused QKV projection; V output tf32-rounded in epilogue (mask bit 2)
    gemm_tc3<<<dim3(kC / 128, kT / 128, 3), 256, GEMM_SMEM_BYTES>>>(
        xr, wr + 0 * CC, wr + 1 * CC, wr + 2 * CC, qp, kp, vp, kT, kC, kC, 4u);

    rope_kernel<<<kT, 256>>>(qp, kp);

    attn_tc2<<<dim3(kT / 128, kH), 512, ATTN_SMEM_BYTES>>>(qp, kp, vp, cp);

    // Output projection (no rounding)
    gemm_tc3<<<dim3(kC / 128, kT / 128, 1), 256, GEMM_SMEM_BYTES>>>(
        cp, wr + 3 * CC, wr + 3 * CC, wr + 3 * CC, out, out, out, kT, kC, kC, 0u);
}

// round 9
// speedup vs baseline: 1.0682x; 1.0682x over previous
#include <cuda_runtime.h>
#include <math.h>
#include <stdint.h>

// Problem constants
constexpr int kT = 4096;
constexpr int kC = 2048;
constexpr int kH = 16;
constexpr int kD = 128;
constexpr float kScale = 0.08838834764831845f;

// Scratch (device globals — no cudaMalloc allowed)
__device__ float g_q[kT * kC];
__device__ float g_k[kT * kC];
__device__ float g_v[kT * kC];
__device__ float g_ctx[kT * kC];
__device__ float g_xr[kT * kC];          // tf32-rounded x
__device__ float g_wr[4 * kC * kC];      // tf32-rounded wq,wk,wv,wo

// ---------------------------------------------------------------------------
__device__ __forceinline__ uint32_t smem_u32(const void* p) {
    uint32_t a;
    asm("{ .reg .u64 t; cvta.to.shared.u64 t, %1; cvt.u32.u64 %0, t; }"
        : "=r"(a) : "l"(p));
    return a;
}

__device__ __forceinline__ void cp_async16(uint32_t saddr, const void* gaddr) {
    asm volatile("cp.async.cg.shared.global [%0], [%1], 16;"
                 :: "r"(saddr), "l"(gaddr));
}
#define CP_COMMIT() asm volatile("cp.async.commit_group;" ::: "memory")

__device__ __forceinline__ float round_tf32(float x) {
    uint32_t u;
    asm("cvt.rna.tf32.f32 %0, %1;" : "=r"(u) : "f"(x));
    return __uint_as_float(u);
}

// mma.sync m16n8k8 tf32: D(16x8 f32) += A(16x8) * B(8x8)
__device__ __forceinline__ void mma_tf32(float* d, const uint32_t* a,
                                         const uint32_t* b) {
    asm volatile(
        "mma.sync.aligned.m16n8k8.row.col.f32.tf32.tf32.f32 "
        "{%0,%1,%2,%3}, {%4,%5,%6,%7}, {%8,%9}, {%0,%1,%2,%3};"
        : "+f"(d[0]), "+f"(d[1]), "+f"(d[2]), "+f"(d[3])
        : "r"(a[0]), "r"(a[1]), "r"(a[2]), "r"(a[3]), "r"(b[0]), "r"(b[1]));
}

// ---------------------------------------------------------------------------
// Fused elementwise tf32 rounding: y=0 -> x, y in 1..4 -> weights.
// ---------------------------------------------------------------------------
__global__ void round_all(const float* __restrict__ x,
                          const float* __restrict__ wq,
                          const float* __restrict__ wk,
                          const float* __restrict__ wv,
                          const float* __restrict__ wo,
                          float* __restrict__ xr, float* __restrict__ wr) {
    const int y = blockIdx.y;
    const float* src;
    float* dst;
    int n4;
    const int CC = kC * kC;
    if (y == 0) { src = x;  dst = xr;           n4 = kT * kC / 4; }
    else if (y == 1) { src = wq; dst = wr;          n4 = CC / 4; }
    else if (y == 2) { src = wk; dst = wr + CC;     n4 = CC / 4; }
    else if (y == 3) { src = wv; dst = wr + 2 * CC; n4 = CC / 4; }
    else             { src = wo; dst = wr + 3 * CC; n4 = CC / 4; }
    int i = blockIdx.x * blockDim.x + threadIdx.x;
    if (i < n4) {
        float4 v = ((const float4*)src)[i];
        v.x = round_tf32(v.x); v.y = round_tf32(v.y);
        v.z = round_tf32(v.z); v.w = round_tf32(v.w);
        ((float4*)dst)[i] = v;
    }
}

// ---------------------------------------------------------------------------
// TF32 tensor-core GEMM: C[m,n] = sum_k A[m,k] * B[n,k]
// CTA tile 128x128x32, 4 warps, warp tile 64x64 (128 B LDS per MMA — at the
// smem crossbar ceiling instead of 1.5x over it). 3-stage cp.async pipeline,
// XOR-swizzled smem. blockIdx.z selects (B, C); roundMask bit z rounds output.
// ---------------------------------------------------------------------------
constexpr int GLD = 32;
constexpr int GSTAGE_FLOATS = 2 * 128 * GLD;
constexpr int GEMM_SMEM_BYTES = 3 * GSTAGE_FLOATS * 4;  // 98304

__device__ __forceinline__ int swoff(int r, int c) {
    return r * GLD + ((((c >> 2) ^ (r & 7)) << 2) | (c & 3));
}

__global__ __launch_bounds__(128, 2) void gemm_tc3(
    const float* __restrict__ A,
    const float* __restrict__ B0, const float* __restrict__ B1,
    const float* __restrict__ B2,
    float* __restrict__ C0, float* __restrict__ C1, float* __restrict__ C2,
    int M, int N, int K, unsigned roundMask) {
    const float* B = (blockIdx.z == 0) ? B0 : (blockIdx.z == 1) ? B1 : B2;
    float* C = (blockIdx.z == 0) ? C0 : (blockIdx.z == 1) ? C1 : C2;
    const bool doRound = (roundMask >> blockIdx.z) & 1u;

    extern __shared__ float smf[];
    const uint32_t sb = smem_u32(smf);
    const int tid = threadIdx.x;
    const int lane = tid & 31;
    const int wid = tid >> 5;      // 0..3
    const int warp_m = wid & 1;    // rows warp_m*64
    const int warp_n = wid >> 1;   // cols warp_n*64
    const int bm = blockIdx.y * 128;
    const int bn = blockIdx.x * 128;

    const int lrow = tid >> 3;     // 0..15 (+j*16 -> 0..127)
    const int cc8 = tid & 7;       // chunk 0..7

    float d[4][8][4];
#pragma unroll
    for (int mi = 0; mi < 4; mi++)
#pragma unroll
        for (int ni = 0; ni < 8; ni++)
#pragma unroll
            for (int j = 0; j < 4; j++) d[mi][ni][j] = 0.0f;

    const int nStages = K / 32;

    auto prefetch = [&](int s) {
        const int buf = s % 3;
        const uint32_t ab = sb + buf * GSTAGE_FLOATS * 4;
        const uint32_t bb = ab + 128 * GLD * 4;
        const int k0 = s * 32;
#pragma unroll
        for (int j = 0; j < 8; j++) {
            const int row = lrow + j * 16;
            const int scc = cc8 ^ (row & 7);
            const uint32_t soff = (uint32_t)(row * GLD + scc * 4) * 4;
            cp_async16(ab + soff, &A[(size_t)(bm + row) * K + k0 + cc8 * 4]);
            cp_async16(bb + soff, &B[(size_t)(bn + row) * K + k0 + cc8 * 4]);
        }
        CP_COMMIT();
    };

    prefetch(0);
    prefetch(1);

    const int fr = lane >> 2;
    const int fc = lane & 3;

    for (int s = 0; s < nStages; s++) {
        if (s < nStages - 1) {
            asm volatile("cp.async.wait_group 1;" ::: "memory");
        } else {
            asm volatile("cp.async.wait_group 0;" ::: "memory");
        }
        __syncthreads();
        if (s + 2 < nStages) prefetch(s + 2);

        const int buf = s % 3;
        const uint32_t* As = (const uint32_t*)(smf + buf * GSTAGE_FLOATS);
        const uint32_t* Bs = As + 128 * GLD;

#pragma unroll
        for (int kk = 0; kk < 4; kk++) {
            const int c0 = kk * 8 + fc;
            uint32_t a[4][4];
#pragma unroll
            for (int mi = 0; mi < 4; mi++) {
                const int r0 = warp_m * 64 + mi * 16 + fr;
                a[mi][0] = As[swoff(r0, c0)];
                a[mi][1] = As[swoff(r0 + 8, c0)];
                a[mi][2] = As[swoff(r0, c0 + 4)];
                a[mi][3] = As[swoff(r0 + 8, c0 + 4)];
            }
            uint32_t b[8][2];
#pragma unroll
            for (int ni = 0; ni < 8; ni++) {
                const int n0 = warp_n * 64 + ni * 8 + fr;
                b[ni][0] = Bs[swoff(n0, c0)];
                b[ni][1] = Bs[swoff(n0, c0 + 4)];
            }
#pragma unroll
            for (int mi = 0; mi < 4; mi++)
#pragma unroll
                for (int ni = 0; ni < 8; ni++)
                    mma_tf32(d[mi][ni], a[mi], b[ni]);
        }
    }

#pragma unroll
    for (int mi = 0; mi < 4; mi++) {
        const int row = bm + warp_m * 64 + mi * 16 + fr;
#pragma unroll
        for (int ni = 0; ni < 8; ni++) {
            const int col = bn + warp_n * 64 + ni * 8 + fc * 2;
            float2 v0 = make_float2(d[mi][ni][0], d[mi][ni][1]);
            float2 v1 = make_float2(d[mi][ni][2], d[mi][ni][3]);
            if (doRound) {
                v0.x = round_tf32(v0.x); v0.y = round_tf32(v0.y);
                v1.x = round_tf32(v1.x); v1.y = round_tf32(v1.y);
            }
            *(float2*)&C[(size_t)row * N + col] = v0;
            *(float2*)&C[(size_t)(row + 8) * N + col] = v1;
        }
    }
}

// ---------------------------------------------------------------------------
// RoPE in-place on Q and K laid out [T, H*D].
// Q: rotated, scaled by kScale, tf32-rounded. K: rotated, tf32-rounded.
// ---------------------------------------------------------------------------
__global__ void rope_kernel(float* __restrict__ Q, float* __restrict__ K) {
    const int t = blockIdx.x;
    const float ft = (float)t;
    for (int p = threadIdx.x; p < kH * 64; p += blockDim.x) {
        const int h = p >> 6;
        const int i = p & 63;
        const float inv = __expf(-(float)i * 0.14391157f);
        float s, c;
        sincosf(ft * inv, &s, &c);
        const size_t base = (size_t)t * kC + h * kD;
        {
            float x1 = Q[base + i], x2 = Q[base + 64 + i];
            Q[base + i]      = round_tf32((x1 * c - x2 * s) * kScale);
            Q[base + 64 + i] = round_tf32((x2 * c + x1 * s) * kScale);
        }
        {
            float x1 = K[base + i], x2 = K[base + 64 + i];
            K[base + i]      = round_tf32(x1 * c - x2 * s);
            K[base + 64 + i] = round_tf32(x2 * c + x1 * s);
        }
    }
}

// ---------------------------------------------------------------------------
// Tensor-core block-sparse flash attention (round-7 proven config).
// One CTA per (q-PAIR, head): 128 q rows, 256 threads / 8 warps.
// QK warp tile 32x32 (grid 4x2); PV warp tile 32x64 (4x2).
// Software-pipelined cp.async K/V; heavy CTAs first.
// ---------------------------------------------------------------------------
constexpr int AQLD = 132;   // Q [128][132], K [64][132]
constexpr int AVLD = 136;   // V [64][136]
constexpr int APLD = 68;    // S/P [128][68]
constexpr int ATTN_SMEM_FLOATS =
    128 * AQLD + 64 * AQLD + 64 * AVLD + 128 * APLD + 128;
constexpr int ATTN_SMEM_BYTES = ATTN_SMEM_FLOATS * 4;   // 171,520 B

__global__ __launch_bounds__(256, 1) void attn_tc2(const float* __restrict__ Q,
                                                   const float* __restrict__ K,
                                                   const float* __restrict__ V,
                                                   float* __restrict__ Ctx) {
    extern __shared__ float sm[];
    float* Qs = sm;                         // [128][132]
    float* Ks = Qs + 128 * AQLD;            // [64][132]
    float* Vs = Ks + 64 * AQLD;             // [64][136]
    float* Ps = Vs + 64 * AVLD;             // [128][68]
    float* Cr = Ps + 128 * APLD;            // [128]

    const uint32_t sb = smem_u32(sm);
    const uint32_t QsA = sb;
    const uint32_t KsA = sb + 128 * AQLD * 4;
    const uint32_t VsA = KsA + 64 * AQLD * 4;

    const int qp = (gridDim.x - 1) - blockIdx.x;   // heavy-first
    const int h = blockIdx.y;
    const int q0 = 2 * qp;
    const int q1 = q0 + 1;
    const int tid = threadIdx.x;
    const int lane = tid & 31;
    const int wid = tid >> 5;
    const int wm = wid & 3;
    const int wn = wid >> 2;
    const int fr = lane >> 2;
    const int fc = lane & 3;
    const int srow = tid >> 1;
    const int shalf = tid & 1;

    auto is_allowed = [&](int t) {
        const bool glob = (t < 2) || ((t & 3) == 0);
        const bool a0 = (t <= q0) && (((q0 - t) <= 16) || glob);
        const bool a1 = ((q1 - t) <= 16) || glob;
        return a0 || a1;
    };

    auto issueK = [&](int t) {
#pragma unroll
        for (int j = 0; j < 8; j++) {
            const int idx = tid * 4 + j * 1024;
            const int rr = idx >> 7;
            const int dd = idx & 127;
            cp_async16(KsA + (uint32_t)(rr * AQLD + dd) * 4,
                       &K[(size_t)(t * 64 + rr) * kC + h * kD + dd]);
        }
        CP_COMMIT();
    };
    auto issueV = [&](int t) {
#pragma unroll
        for (int j = 0; j < 8; j++) {
            const int idx = tid * 4 + j * 1024;
            const int rr = idx >> 7;
            const int dd = idx & 127;
            cp_async16(VsA + (uint32_t)(rr * AVLD + dd) * 4,
                       &V[(size_t)(t * 64 + rr) * kC + h * kD + dd]);
        }
        CP_COMMIT();
    };

    // Q tile (group 0), then K0 (group 1), V0 (group 2)
#pragma unroll
    for (int j = 0; j < 16; j++) {
        const int idx = tid * 4 + j * 1024;
        const int rr = idx >> 7;
        const int dd = idx & 127;
        cp_async16(QsA + (uint32_t)(rr * AQLD + dd) * 4,
                   &Q[(size_t)(qp * 128 + rr) * kC + h * kD + dd]);
    }
    CP_COMMIT();
    int kb = 0;
    issueK(kb);
    issueV(kb);

    float m = -INFINITY, l = 0.0f;
    float o[2][8][4];
#pragma unroll
    for (int mi = 0; mi < 2; mi++)
#pragma unroll
        for (int ni = 0; ni < 8; ni++)
#pragma unroll
            for (int j = 0; j < 4; j++) o[mi][ni][j] = 0.0f;

    const uint32_t* Qsu = (const uint32_t*)Qs;
    const uint32_t* Ksu = (const uint32_t*)Ks;
    const uint32_t* Vsu = (const uint32_t*)Vs;
    const uint32_t* Psu = (const uint32_t*)Ps;

    while (true) {
        int kbn = kb;
        for (int t = kb + 1; t <= q1; t++) {
            if (is_allowed(t)) { kbn = t; break; }
        }
        const bool glob = (kb < 2) || ((kb & 3) == 0);
        const bool allowed0 = (kb <= q0) && (((q0 - kb) <= 16) || glob);
        const bool allowed1 = ((q1 - kb) <= 16) || glob;

        // wait for K(kb) (Q on first iter too); V(kb) may still be in flight
        asm volatile("cp.async.wait_group 1;" ::: "memory");
        __syncthreads();

        // ---- S = Q @ K^T (128x64) : warp tile 32x32 ----
        float s[2][4][4];
#pragma unroll
        for (int mi = 0; mi < 2; mi++)
#pragma unroll
            for (int ni = 0; ni < 4; ni++)
#pragma unroll
                for (int j = 0; j < 4; j++) s[mi][ni][j] = 0.0f;

#pragma unroll
        for (int kk = 0; kk < 16; kk++) {
            const int c0 = kk * 8 + fc;
            uint32_t a[2][4];
#pragma unroll
            for (int mi = 0; mi < 2; mi++) {
                const int r0 = wm * 32 + mi * 16 + fr;
                a[mi][0] = Qsu[r0 * AQLD + c0];
                a[mi][1] = Qsu[(r0 + 8) * AQLD + c0];
                a[mi][2] = Qsu[r0 * AQLD + c0 + 4];
                a[mi][3] = Qsu[(r0 + 8) * AQLD + c0 + 4];
            }
            uint32_t b[4][2];
#pragma unroll
            for (int ni = 0; ni < 4; ni++) {
                const int n0 = wn * 32 + ni * 8 + fr;
                b[ni][0] = Ksu[n0 * AQLD + c0];
                b[ni][1] = Ksu[n0 * AQLD + c0 + 4];
            }
#pragma unroll
            for (int mi = 0; mi < 2; mi++)
#pragma unroll
                for (int ni = 0; ni < 4; ni++)
                    mma_tf32(s[mi][ni], a[mi], b[ni]);
        }

        // Store S fragments
#pragma unroll
        for (int mi = 0; mi < 2; mi++) {
            const int r = wm * 32 + mi * 16 + fr;
#pragma unroll
            for (int ni = 0; ni < 4; ni++) {
                const int c = wn * 32 + ni * 8 + fc * 2;
                *(float2*)&Ps[r * APLD + c] = make_float2(s[mi][ni][0], s[mi][ni][1]);
                *(float2*)&Ps[(r + 8) * APLD + c] = make_float2(s[mi][ni][2], s[mi][ni][3]);
            }
        }
        __syncthreads();   // all QK reads of Ks done; S visible

        // prefetch next K (overlaps softmax+PV)
        issueK(kbn);

        // ---- scalar online softmax (row srow, cols shalf*32..+31) ----
        {
            const bool rowAllowed = (srow < 64) ? allowed0 : allowed1;
            float* prow = &Ps[srow * APLD + shalf * 32];
            if (rowAllowed) {
                float4 sv[8];
#pragma unroll
                for (int j = 0; j < 8; j++) sv[j] = *(const float4*)&prow[j * 4];
                float lm = -INFINITY;
#pragma unroll
                for (int j = 0; j < 8; j++)
                    lm = fmaxf(lm, fmaxf(fmaxf(sv[j].x, sv[j].y), fmaxf(sv[j].z, sv[j].w)));
                lm = fmaxf(lm, __shfl_xor_sync(0xFFFFFFFFu, lm, 1));
                const float mnew = fmaxf(m, lm);
                const float corr = __expf(m - mnew);
                float rs = 0.0f;
#pragma unroll
                for (int j = 0; j < 8; j++) {
                    sv[j].x = round_tf32(__expf(sv[j].x - mnew));
                    sv[j].y = round_tf32(__expf(sv[j].y - mnew));
                    sv[j].z = round_tf32(__expf(sv[j].z - mnew));
                    sv[j].w = round_tf32(__expf(sv[j].w - mnew));
                    rs += (sv[j].x + sv[j].y) + (sv[j].z + sv[j].w);
                    *(float4*)&prow[j * 4] = sv[j];
                }
                rs += __shfl_xor_sync(0xFFFFFFFFu, rs, 1);
                l = l * corr + rs;
                m = mnew;
                if (shalf == 0) Cr[srow] = corr;
            } else {
                const float4 z = make_float4(0.f, 0.f, 0.f, 0.f);
#pragma unroll
                for (int j = 0; j < 8; j++) *(float4*)&prow[j * 4] = z;
                if (shalf == 0) Cr[srow] = 1.0f;
            }
        }

        // wait for V(kb) (K(kbn) stays in flight), then publish P/Cr/V
        asm volatile("cp.async.wait_group 1;" ::: "memory");
        __syncthreads();

        // ---- O = O*corr + P @ V (128x128) : warp tile 32x64 ----
#pragma unroll
        for (int mi = 0; mi < 2; mi++) {
            const float c0r = Cr[wm * 32 + mi * 16 + fr];
            const float c1r = Cr[wm * 32 + mi * 16 + 8 + fr];
#pragma unroll
            for (int ni = 0; ni < 8; ni++) {
                o[mi][ni][0] *= c0r; o[mi][ni][1] *= c0r;
                o[mi][ni][2] *= c1r; o[mi][ni][3] *= c1r;
            }
        }
#pragma unroll
        for (int kk = 0; kk < 8; kk++) {
            const int c0 = kk * 8 + fc;
            uint32_t a[2][4];
#pragma unroll
            for (int mi = 0; mi < 2; mi++) {
                const int r0 = wm * 32 + mi * 16 + fr;
                a[mi][0] = Psu[r0 * APLD + c0];
                a[mi][1] = Psu[(r0 + 8) * APLD + c0];
                a[mi][2] = Psu[r0 * APLD + c0 + 4];
                a[mi][3] = Psu[(r0 + 8) * APLD + c0 + 4];
            }
            uint32_t b[8][2];
#pragma unroll
            for (int ni = 0; ni < 8; ni++) {
                const int n0 = wn * 64 + ni * 8 + fr;
                b[ni][0] = Vsu[c0 * AVLD + n0];
                b[ni][1] = Vsu[(c0 + 4) * AVLD + n0];
            }
#pragma unroll
            for (int mi = 0; mi < 2; mi++)
#pragma unroll
                for (int ni = 0; ni < 8; ni++)
                    mma_tf32(o[mi][ni], a[mi], b[ni]);
        }
        __syncthreads();   // PV reads of Vs/Ps done

        // prefetch next V (overlaps next tile's QK+softmax)
        issueV(kbn);

        if (kbn == kb) break;
        kb = kbn;
    }

    // Drain, publish 1/l, store
    asm volatile("cp.async.wait_group 0;" ::: "memory");
    __syncthreads();
    if (shalf == 0) Cr[srow] = 1.0f / l;
    __syncthreads();
#pragma unroll
    for (int mi = 0; mi < 2; mi++) {
        const float inv0 = Cr[wm * 32 + mi * 16 + fr];
        const float inv1 = Cr[wm * 32 + mi * 16 + 8 + fr];
        const int row0 = qp * 128 + wm * 32 + mi * 16 + fr;
#pragma unroll
        for (int ni = 0; ni < 8; ni++) {
            const int col = h * kD + wn * 64 + ni * 8 + fc * 2;
            *(float2*)&Ctx[(size_t)row0 * kC + col] =
                make_float2(round_tf32(o[mi][ni][0] * inv0),
                            round_tf32(o[mi][ni][1] * inv0));
            *(float2*)&Ctx[(size_t)(row0 + 8) * kC + col] =
                make_float2(round_tf32(o[mi][ni][2] * inv1),
                            round_tf32(o[mi][ni][3] * inv1));
        }
    }
}

// ---------------------------------------------------------------------------
extern "C" void kernel_launch(void* const* d_in, const int* in_sizes, int n_in,
                              void* d_out, int out_size) {
    const float* x  = (const float*)d_in[0];
    const float* wq = (const float*)d_in[1];
    const float* wk = (const float*)d_in[2];
    const float* wv = (const float*)d_in[3];
    const float* wo = (const float*)d_in[4];
    float* out = (float*)d_out;

    float *qp, *kp, *vp, *cp, *xr, *wr;
    cudaGetSymbolAddress((void**)&qp, g_q);
    cudaGetSymbolAddress((void**)&kp, g_k);
    cudaGetSymbolAddress((void**)&vp, g_v);
    cudaGetSymbolAddress((void**)&cp, g_ctx);
    cudaGetSymbolAddress((void**)&xr, g_xr);
    cudaGetSymbolAddress((void**)&wr, g_wr);

    cudaFuncSetAttribute(gemm_tc3, cudaFuncAttributeMaxDynamicSharedMemorySize,
                         GEMM_SMEM_BYTES);
    cudaFuncSetAttribute(attn_tc2, cudaFuncAttributeMaxDynamicSharedMemorySize,
                         ATTN_SMEM_BYTES);

    const int CC = kC * kC;

    round_all<<<dim3(kT * kC / 4 / 256, 5), 256>>>(x, wq, wk, wv, wo, xr, wr);

    // Fused QKV projection; V output tf32-rounded in epilogue (mask bit 2)
    gemm_tc3<<<dim3(kC / 128, kT / 128, 3), 128, GEMM_SMEM_BYTES>>>(
        xr, wr + 0 * CC, wr + 1 * CC, wr + 2 * CC, qp, kp, vp, kT, kC, kC, 4u);

    rope_kernel<<<kT, 256>>>(qp, kp);

    attn_tc2<<<dim3(kT / 128, kH), 256, ATTN_SMEM_BYTES>>>(qp, kp, vp, cp);

    // Output projection (no rounding)
    gemm_tc3<<<dim3(kC / 128, kT / 128, 1), 128, GEMM_SMEM_BYTES>>>(
        cp, wr + 3 * CC, wr + 3 * CC, wr + 3 * CC, out, out, out, kT, kC, kC, 0u);
}